// round 12
// baseline (speedup 1.0000x reference)
#include <cuda_runtime.h>
#include <cstdint>

#define Nn 1024
#define Hh 100
#define Gg 400
#define KE 125
#define Ll 40
#define EPSV 1e-20f

// ---------------- scratch (device globals; no allocation allowed) ----------------
__device__ float g_E[Nn * KE];   // embeddings [1024,125]
__device__ float g_P[Nn * Gg];   // layer0 input projection (gemm output)
__device__ float g_P1[Nn * Gg];  // layer1 input projection (stage B output)
__device__ float g_H0[Nn * Hh];  // layer0 hidden states
__device__ float g_H1[Nn * Hh];  // layer1 hidden states
__device__ int g_cnt0;           // h0 rows < cnt0 published
__device__ int g_cnt1;           // P1 rows < cnt1 published
__device__ float g_EA[Nn];
__device__ float g_EB[Nn];
__device__ float g_S;

// ---------------- helpers ----------------
__device__ __forceinline__ float tanhap(float x) {
    float r;
    asm("tanh.approx.f32 %0, %1;" : "=f"(r) : "f"(x));
    return r;
}
#define FMA2(acc, a, b) asm("fma.rn.f32x2 %0, %1, %2, %0;" : "+l"(acc) : "l"(a), "l"(b))
#define ADD2(d, a, b) asm("add.rn.f32x2 %0, %1, %2;" : "=l"(d) : "l"(a), "l"(b))
__device__ __forceinline__ float unpack_sum(unsigned long long v) {
    float lo, hi;
    asm("mov.b64 {%0, %1}, %2;" : "=f"(lo), "=f"(hi) : "l"(v));
    return lo + hi;
}
__device__ __forceinline__ int ld_acq(const int* p) {
    int v;
    asm volatile("ld.acquire.gpu.b32 %0, [%1];" : "=r"(v) : "l"(p) : "memory");
    return v;
}
__device__ __forceinline__ void st_rel(int* p, int v) {
    asm volatile("st.release.gpu.b32 [%0], %1;" :: "l"(p), "r"(v) : "memory");
}
__device__ __forceinline__ float4 ldg_cg4(const float4* p) {
    float4 v;
    asm volatile("ld.global.cg.v4.f32 {%0,%1,%2,%3}, [%4];"
                 : "=f"(v.x), "=f"(v.y), "=f"(v.z), "=f"(v.w) : "l"(p));
    return v;
}
__device__ __forceinline__ float ldg_cg1(const float* p) {
    float v;
    asm volatile("ld.global.cg.f32 %0, [%1];" : "=f"(v) : "l"(p));
    return v;
}

// ---------------- K0: embedding gather ----------------
__global__ void gather_emb(const int* __restrict__ wi, const int* __restrict__ ti,
                           const float* __restrict__ wt, const float* __restrict__ tt) {
    int t = blockIdx.x;
    int w = wi[t];
    int g = ti[t];
    for (int j = threadIdx.x; j < KE; j += blockDim.x)
        g_E[t * KE + j] = (j < 100) ? wt[w * 100 + j] : tt[g * 25 + (j - 100)];
}

// ---------------- K0b: reset progress counters (every launch / graph replay) ----------------
__global__ void zero_cnt() {
    if (threadIdx.x == 0) { g_cnt0 = 0; g_cnt1 = 0; }
}

// ---------------- K1: P0 = E @ Wih0^T + b_ih0 + b_hh0 ----------------
__global__ __launch_bounds__(256) void gemm_bias(const float* __restrict__ X,
                                                 const float* __restrict__ W,
                                                 const float* __restrict__ b1,
                                                 const float* __restrict__ b2,
                                                 float* __restrict__ C, int K) {
    __shared__ float Xs[64 * 127];
    __shared__ float Ws[32 * 127];
    int m0 = blockIdx.y * 64;
    int n0 = blockIdx.x * 32;
    int tid = threadIdx.x;

    for (int idx = tid; idx < 64 * K; idx += 256) {
        int r = idx / K, c = idx - r * K;
        Xs[r * 127 + c] = X[(m0 + r) * K + c];
    }
    for (int idx = tid; idx < 32 * K; idx += 256) {
        int r = idx / K, c = idx - r * K;
        int n = n0 + r;
        Ws[r * 127 + c] = (n < Gg) ? W[n * K + c] : 0.f;
    }
    __syncthreads();

    int ty = tid >> 5, tx = tid & 31;
    float acc[8] = {0, 0, 0, 0, 0, 0, 0, 0};
    for (int k = 0; k < K; k++) {
        float wv = Ws[tx * 127 + k];
#pragma unroll
        for (int r = 0; r < 8; r++)
            acc[r] = fmaf(Xs[(ty + 8 * r) * 127 + k], wv, acc[r]);
    }
    int n = n0 + tx;
    if (n < Gg) {
        float bb = b1[n] + b2[n];
#pragma unroll
        for (int r = 0; r < 8; r++)
            C[(m0 + ty + 8 * r) * Gg + n] = acc[r] + bb;
    }
}

// ---------------- K2: 3-stage LSTM pipeline, distance-2 double-buffering ----------------
// grid=3 x 448 (13 compute warps + 1 comm warp). role 0 (A): layer0 recurrence;
// 1 (B): layer1 input proj; 2 (C): layer1 recurrence.
// Compute thread tid<400: unit u=tid>>2, gate g=tid&3, row r=g*100+u.
// Distance-2 buffering: every STS at a step's top writes data LDG'd a full step
// earlier (register buffer) -> no barrier-on-STS-drain. Lookahead spins at t+4.
// B uses the R10-PROVEN obuf permutation pair: STS at row index r after the dot,
// coalesced STG from obuf[..][tid] at the next step's top. (R11's o_reg stored
// row r's value at column tid -- scrambled P1; that was R11's bug.)
__global__ __launch_bounds__(448, 1) void lstm_pipe(const float* __restrict__ Whh0,
                                                    const float* __restrict__ Wih1,
                                                    const float* __restrict__ Whh1,
                                                    const float* __restrict__ bih1,
                                                    const float* __restrict__ bhh1) {
    __shared__ __align__(16) float h_sh[2][Hh];   // A/C recurrent state (double buffered)
    __shared__ __align__(16) float hbuf[2][Hh];   // B: staged h0 rows
    __shared__ __align__(16) float pbuf[2][Gg];   // A/C: staged additive rows
    __shared__ __align__(16) float obuf[2][Gg];   // B: gate outputs awaiting writeback

    const int role = blockIdx.x;
    const int tid = threadIdx.x;
    const bool iscomp = tid < 400;
    const int u = tid >> 2;      // unit 0..99
    const int g = tid & 3;       // gate 0:i 1:f 2:g 3:o
    const int r = g * 100 + u;   // weight row
    const unsigned shmask = (tid < 384) ? 0xffffffffu : 0x0000ffffu;

    const float* W = (role == 0) ? Whh0 : (role == 1) ? Wih1 : Whh1;
    const float* Pin = (role == 0) ? g_P : g_P1;

    // full weight row in registers: 25 ulonglong2 = 50 u64 regs
    unsigned long long wv[50];
    if (iscomp) {
        const ulonglong2* Wr = reinterpret_cast<const ulonglong2*>(W + r * Hh);
#pragma unroll
        for (int j = 0; j < 25; j++) {
            ulonglong2 v = Wr[j];
            wv[2 * j] = v.x;
            wv[2 * j + 1] = v.y;
        }
    }
    float bb = 0.f;
    if (role == 1 && iscomp) bb = bih1[r] + bhh1[r];
    float c = 0.f;
    if (role != 1 && tid < Hh) h_sh[0][tid] = 0.f;

    int seen = 0;        // spin lane's cached counter
    float p_reg = 0.f;   // A/C: additive row t+1 (register buffer)
    float4 hreg = make_float4(0.f, 0.f, 0.f, 0.f);  // B comm lanes: h0 row t+1 chunk

    // ---- prologue: confirm rows 0..3; stage row 0 in smem, row 1 in regs ----
    if (!iscomp && tid >= 416) {
        int lane = tid - 416;
        if (role == 1) {
            if (lane == 26) {
                while ((seen = ld_acq(&g_cnt0)) < 4) {}
            }
        } else if (role == 2) {
            if (lane == 0) {
                while ((seen = ld_acq(&g_cnt1)) < 4) {}
            }
        }
    }
    __syncthreads();  // spin confirmed for all prologue loads below
    if (iscomp && role != 1) {
        pbuf[0][tid] = ldg_cg1(Pin + tid);   // row 0 -> smem
        p_reg = ldg_cg1(Pin + Gg + tid);     // row 1 -> reg
    }
    if (!iscomp && role == 1) {
        int lane = tid - 416;
        if (lane < 25) {
            reinterpret_cast<float4*>(hbuf[0])[lane] =
                ldg_cg4(reinterpret_cast<const float4*>(g_H0) + lane);          // row 0
            hreg = ldg_cg4(reinterpret_cast<const float4*>(g_H0 + Hh) + lane);  // row 1
        }
    }
    __syncthreads();

    for (int t = 0; t < Nn; t++) {
        if (iscomp) {
            // ---- top: stores of data loaded >= 1 step ago, then distance-2 prefetch ----
            if (role == 1) {
                if (t >= 1) __stcg(&g_P1[(t - 1) * Gg + tid], obuf[(t - 1) & 1][tid]);
            } else {
                if (t + 1 < Nn) pbuf[(t + 1) & 1][tid] = p_reg;             // STS row t+1
                if (t + 2 < Nn) p_reg = ldg_cg1(Pin + (t + 2) * Gg + tid);  // LDG row t+2
            }

            // ---- dot ----
            const float* hin = (role == 1) ? hbuf[t & 1] : h_sh[t & 1];
            const ulonglong2* h2 = reinterpret_cast<const ulonglong2*>(hin);
            unsigned long long a0 = 0ull, a1 = 0ull, a2 = 0ull, a3 = 0ull;
#pragma unroll
            for (int j = 0; j < 25; j++) {
                ulonglong2 hv = h2[j];  // LDS.128 broadcast
                if (j & 1) {
                    FMA2(a2, wv[2 * j], hv.x);
                    FMA2(a3, wv[2 * j + 1], hv.y);
                } else {
                    FMA2(a0, wv[2 * j], hv.x);
                    FMA2(a1, wv[2 * j + 1], hv.y);
                }
            }
            ADD2(a0, a0, a1);
            ADD2(a2, a2, a3);
            ADD2(a0, a0, a2);
            float a = unpack_sum(a0);

            if (role == 1) {
                obuf[t & 1][r] = a + bb;  // STS at row r (dot-dependent only); STG next step
            } else {
                float v = a + pbuf[t & 1][r];
                float act = (g == 2) ? tanhap(v) : fmaf(0.5f, tanhap(0.5f * v), 0.5f);
                float vf = __shfl_sync(shmask, act, 1, 4);
                float vg = __shfl_sync(shmask, act, 2, 4);
                float vo = __shfl_sync(shmask, act, 3, 4);
                if (g == 0) {  // owner lane: own act = i gate
                    c = fmaf(vf, c, act * vg);
                    float hk = vo * tanhap(c);
                    h_sh[(t + 1) & 1][u] = hk;
                    if (role == 0) __stcg(&g_H0[t * Hh + u], hk);
                    else g_H1[t * Hh + u] = hk;
                }
            }
        } else if (tid >= 416) {
            int lane = tid - 416;
            if (role == 0) {
                if (lane == 0 && (t & 7) == 0 && t > 0) st_rel(&g_cnt0, t);  // rows < t
            } else if (role == 1) {
                if (lane < 25) {
                    if (t + 1 < Nn)
                        reinterpret_cast<float4*>(hbuf[(t + 1) & 1])[lane] = hreg;  // STS (old data)
                    if (t + 2 < Nn)
                        hreg = ldg_cg4(reinterpret_cast<const float4*>(g_H0 + (t + 2) * Hh) + lane);
                } else if (lane == 25) {
                    if ((t & 7) == 0 && t > 0) st_rel(&g_cnt1, t - 1);  // rows < t-1 (stored <= step t-1)
                } else if (lane == 26) {
                    if (t + 3 < Nn && seen < t + 4) {
                        while ((seen = ld_acq(&g_cnt0)) < t + 4) {}
                    }
                }
            } else {
                if (lane == 0 && t + 3 < Nn && seen < t + 4) {
                    while ((seen = ld_acq(&g_cnt1)) < t + 4) {}
                }
            }
        }
        __syncthreads();
    }
    // epilogue: B writes back its final row; final releases
    if (role == 1 && iscomp)
        __stcg(&g_P1[(Nn - 1) * Gg + tid], obuf[(Nn - 1) & 1][tid]);
    __syncthreads();
    if (tid == 416) {
        if (role == 0) st_rel(&g_cnt0, Nn);
        else if (role == 1) st_rel(&g_cnt1, Nn);
    }
}

// ---------------- K5b: fold scorer weights + EA/EB/S ----------------
__global__ __launch_bounds__(1024) void score_vec(const float* __restrict__ Wh2h,
                                                  const float* __restrict__ bh2h,
                                                  const float* __restrict__ Wsc,
                                                  const float* __restrict__ bsc) {
    __shared__ float u_sh[2 * Hh + 1];
    __shared__ float red[Nn];
    int i = threadIdx.x;

    if (i < 200) {
        int k = (i < 100) ? i : i - 100;
        int which = (i < 100) ? 0 : 1;
        const float* base = Wh2h + which * 100 + k;
        float s = 0.f;
        for (int m = 0; m < Hh; m++) s = fmaf(base[m * 200], Wsc[m], s);
        u_sh[which * 100 + k] = s;
    } else if (i == 200) {
        float c0 = bsc[0];
        for (int m = 0; m < Hh; m++) c0 = fmaf(bh2h[m], Wsc[m], c0);
        u_sh[200] = c0;
    }
    __syncthreads();

    const float* h = g_H1 + i * Hh;
    float sA = 0.f, sB = 0.f;
    for (int j = 0; j < Hh; j++) {
        float hv = h[j];
        sA = fmaf(hv, u_sh[j], sA);
        sB = fmaf(hv, u_sh[100 + j], sB);
    }
    float ea = __expf(sA);
    float eb = __expf(sB + u_sh[200]);
    g_EA[i] = ea;
    g_EB[i] = eb;
    red[i] = ea;
    __syncthreads();
    for (int s = 512; s > 0; s >>= 1) {
        if (i < s) red[i] += red[i + s];
        __syncthreads();
    }
    if (i == 0) g_S = red[0];
}

// ---------------- K5c: scores[i][j] = EA[i]*EB[j] / (S*EB[j] + eps) ----------------
__global__ void fill_scores(float* __restrict__ out) {
    int i = blockIdx.x;
    float ea = g_EA[i];
    float S = g_S;
    for (int j = threadIdx.x; j < Nn; j += blockDim.x) {
        float eb = g_EB[j];
        out[i * Nn + j] = __fdividef(ea * eb, fmaf(S, eb, EPSV));
    }
}

// ---------------- K5d: labels ----------------
__global__ void fill_labels(const float* __restrict__ Wlab, const float* __restrict__ blab,
                            float* __restrict__ out) {
    __shared__ float hsh[Hh];
    __shared__ float esh[Ll];
    int r = blockIdx.x;  // 0..1022
    int tid = threadIdx.x;
    const float* h = g_H1 + (r + 1) * Hh;
    for (int j = tid; j < Hh; j += 64) hsh[j] = h[j];
    __syncthreads();
    if (tid < Ll) {
        float a = blab[tid];
        const float* wr = Wlab + tid * Hh;
        for (int j = 0; j < Hh; j++) a = fmaf(hsh[j], wr[j], a);
        esh[tid] = __expf(a);
    }
    __syncthreads();
    if (tid < Ll) {
        float s = 0.f;
        for (int j = 0; j < Ll; j++) s += esh[j];
        out[Nn * Nn + r * Ll + tid] = __fdividef(esh[tid], s + EPSV);
    }
}

// ---------------- launch ----------------
extern "C" void kernel_launch(void* const* d_in, const int* in_sizes, int n_in,
                              void* d_out, int out_size) {
    const int* wi = (const int*)d_in[0];
    const int* ti = (const int*)d_in[1];
    const float* wt = (const float*)d_in[2];
    const float* tt = (const float*)d_in[3];
    const float* Wih0 = (const float*)d_in[4];
    const float* Whh0 = (const float*)d_in[5];
    const float* bih0 = (const float*)d_in[6];
    const float* bhh0 = (const float*)d_in[7];
    const float* Wih1 = (const float*)d_in[8];
    const float* Whh1 = (const float*)d_in[9];
    const float* bih1 = (const float*)d_in[10];
    const float* bhh1 = (const float*)d_in[11];
    const float* Wh2h = (const float*)d_in[12];
    const float* bh2h = (const float*)d_in[13];
    const float* Wsc = (const float*)d_in[14];
    const float* bsc = (const float*)d_in[15];
    const float* Wlab = (const float*)d_in[16];
    const float* blab = (const float*)d_in[17];
    float* out = (float*)d_out;

    float *pE, *pP;
    cudaGetSymbolAddress((void**)&pE, g_E);
    cudaGetSymbolAddress((void**)&pP, g_P);

    dim3 gg(13, 16);

    gather_emb<<<Nn, 128>>>(wi, ti, wt, tt);
    zero_cnt<<<1, 32>>>();
    gemm_bias<<<gg, 256>>>(pE, Wih0, bih0, bhh0, pP, KE);
    lstm_pipe<<<3, 448>>>(Whh0, Wih1, Whh1, bih1, bhh1);
    score_vec<<<1, 1024>>>(Wh2h, bh2h, Wsc, bsc);
    fill_scores<<<Nn, 256>>>(out);
    fill_labels<<<Nn - 1, 64>>>(Wlab, blab, out);
}

// round 13
// speedup vs baseline: 1.0041x; 1.0041x over previous
#include <cuda_runtime.h>
#include <cstdint>

#define Nn 1024
#define Hh 100
#define Gg 400
#define KE 125
#define Ll 40
#define EPSV 1e-20f

// ---------------- scratch (device globals; no allocation allowed) ----------------
__device__ float g_E[Nn * KE];   // embeddings [1024,125]
__device__ float g_P[Nn * Gg];   // layer0 input projection, PERMUTED layout (col q(n))
__device__ float g_P1[Nn * Gg];  // layer1 input projection, PERMUTED layout
__device__ float g_H0[Nn * Hh];  // layer0 hidden states
__device__ float g_H1[Nn * Hh];  // layer1 hidden states
__device__ int g_cnt0;           // h0 rows < cnt0 published
__device__ int g_cnt1;           // P1 rows < cnt1 published
__device__ float g_EA[Nn];
__device__ float g_EB[Nn];
__device__ float g_S;

// ---------------- helpers ----------------
__device__ __forceinline__ float tanhap(float x) {
    float r;
    asm("tanh.approx.f32 %0, %1;" : "=f"(r) : "f"(x));
    return r;
}
#define FMA2(acc, a, b) asm("fma.rn.f32x2 %0, %1, %2, %0;" : "+l"(acc) : "l"(a), "l"(b))
#define ADD2(d, a, b) asm("add.rn.f32x2 %0, %1, %2;" : "=l"(d) : "l"(a), "l"(b))
__device__ __forceinline__ float unpack_sum(unsigned long long v) {
    float lo, hi;
    asm("mov.b64 {%0, %1}, %2;" : "=f"(lo), "=f"(hi) : "l"(v));
    return lo + hi;
}
__device__ __forceinline__ int ld_acq(const int* p) {
    int v;
    asm volatile("ld.acquire.gpu.b32 %0, [%1];" : "=r"(v) : "l"(p) : "memory");
    return v;
}
__device__ __forceinline__ void st_rel(int* p, int v) {
    asm volatile("st.release.gpu.b32 [%0], %1;" :: "l"(p), "r"(v) : "memory");
}
__device__ __forceinline__ float4 ldg_cg4(const float4* p) {
    float4 v;
    asm volatile("ld.global.cg.v4.f32 {%0,%1,%2,%3}, [%4];"
                 : "=f"(v.x), "=f"(v.y), "=f"(v.z), "=f"(v.w) : "l"(p));
    return v;
}
__device__ __forceinline__ float ldg_cg1(const float* p) {
    float v;
    asm volatile("ld.global.cg.f32 %0, [%1];" : "=f"(v) : "l"(p));
    return v;
}

// ---------------- K0: embedding gather ----------------
__global__ void gather_emb(const int* __restrict__ wi, const int* __restrict__ ti,
                           const float* __restrict__ wt, const float* __restrict__ tt) {
    int t = blockIdx.x;
    int w = wi[t];
    int g = ti[t];
    for (int j = threadIdx.x; j < KE; j += blockDim.x)
        g_E[t * KE + j] = (j < 100) ? wt[w * 100 + j] : tt[g * 25 + (j - 100)];
}

// ---------------- K0b: reset progress counters (every launch / graph replay) ----------------
__global__ void zero_cnt() {
    if (threadIdx.x == 0) { g_cnt0 = 0; g_cnt1 = 0; }
}

// ---------------- K1: P0' = permuted(E @ Wih0^T + b_ih0 + b_hh0) ----------------
// Output column n stored at q(n) = (n%100)*4 + n/100, so lstm thread tid reads its
// own row r(tid) = (tid&3)*100 + tid>>2 at position tid (coalesced, no smem hop).
__global__ __launch_bounds__(256) void gemm_bias(const float* __restrict__ X,
                                                 const float* __restrict__ W,
                                                 const float* __restrict__ b1,
                                                 const float* __restrict__ b2,
                                                 float* __restrict__ C, int K) {
    __shared__ float Xs[64 * 127];
    __shared__ float Ws[32 * 127];
    int m0 = blockIdx.y * 64;
    int n0 = blockIdx.x * 32;
    int tid = threadIdx.x;

    for (int idx = tid; idx < 64 * K; idx += 256) {
        int r = idx / K, c = idx - r * K;
        Xs[r * 127 + c] = X[(m0 + r) * K + c];
    }
    for (int idx = tid; idx < 32 * K; idx += 256) {
        int r = idx / K, c = idx - r * K;
        int n = n0 + r;
        Ws[r * 127 + c] = (n < Gg) ? W[n * K + c] : 0.f;
    }
    __syncthreads();

    int ty = tid >> 5, tx = tid & 31;
    float acc[8] = {0, 0, 0, 0, 0, 0, 0, 0};
    for (int k = 0; k < K; k++) {
        float wv = Ws[tx * 127 + k];
#pragma unroll
        for (int r = 0; r < 8; r++)
            acc[r] = fmaf(Xs[(ty + 8 * r) * 127 + k], wv, acc[r]);
    }
    int n = n0 + tx;
    if (n < Gg) {
        float bb = b1[n] + b2[n];
        int qn = (n % 100) * 4 + n / 100;  // permuted store column
#pragma unroll
        for (int r = 0; r < 8; r++)
            C[(m0 + ty + 8 * r) * Gg + qn] = acc[r] + bb;
    }
}

// ---------------- K2: 3-stage LSTM pipeline, permuted-P register path ----------------
// grid=3 x 448 (13 compute warps + 1 comm warp). role 0 (A): layer0 recurrence;
// 1 (B): layer1 input proj; 2 (C): layer1 recurrence.
// Compute thread tid<400: unit u=tid>>2, gate g=tid&3, row r=g*100+u.
// Additive rows live in PERMUTED layout (position tid holds row r(tid)), so A/C
// keep them in a per-thread register (coalesced distance-1 prefetch, no pbuf smem)
// and B stores its result directly to g_P1[t*Gg+tid] (no obuf). B's hbuf staged
// distance-2 via register hreg (comm warp's barrier arrival not LDG-dependent).
// Handoff: monotonic counters, 1 st.release per 8 steps, lookahead spins at t+4.
__global__ __launch_bounds__(448, 1) void lstm_pipe(const float* __restrict__ Whh0,
                                                    const float* __restrict__ Wih1,
                                                    const float* __restrict__ Whh1,
                                                    const float* __restrict__ bih1,
                                                    const float* __restrict__ bhh1) {
    __shared__ __align__(16) float h_sh[2][Hh];   // A/C recurrent state (double buffered)
    __shared__ __align__(16) float hbuf[2][Hh];   // B: staged h0 rows

    const int role = blockIdx.x;
    const int tid = threadIdx.x;
    const bool iscomp = tid < 400;
    const int u = tid >> 2;      // unit 0..99
    const int g = tid & 3;       // gate 0:i 1:f 2:g 3:o
    const int r = g * 100 + u;   // weight row
    const unsigned shmask = (tid < 384) ? 0xffffffffu : 0x0000ffffu;

    const float* W = (role == 0) ? Whh0 : (role == 1) ? Wih1 : Whh1;
    const float* Pin = (role == 0) ? g_P : g_P1;  // permuted layout

    // full weight row in registers: 25 ulonglong2 = 50 u64 regs
    unsigned long long wv[50];
    if (iscomp) {
        const ulonglong2* Wr = reinterpret_cast<const ulonglong2*>(W + r * Hh);
#pragma unroll
        for (int j = 0; j < 25; j++) {
            ulonglong2 v = Wr[j];
            wv[2 * j] = v.x;
            wv[2 * j + 1] = v.y;
        }
    }
    float bb = 0.f;
    if (role == 1 && iscomp) bb = bih1[r] + bhh1[r];
    float c = 0.f;
    if (role != 1 && tid < Hh) h_sh[0][tid] = 0.f;

    int seen = 0;        // spin lane's cached counter
    float p_cur = 0.f;   // A/C: additive value for row r(tid), step t
    float4 hreg = make_float4(0.f, 0.f, 0.f, 0.f);  // B comm lanes: h0 row t+1 chunk

    // ---- prologue: confirm rows 0..3; stage row 0 (+ B: h0 rows 0,1) ----
    if (!iscomp && tid >= 416) {
        int lane = tid - 416;
        if (role == 1) {
            if (lane == 26) {
                while ((seen = ld_acq(&g_cnt0)) < 4) {}
            }
        } else if (role == 2) {
            if (lane == 0) {
                while ((seen = ld_acq(&g_cnt1)) < 4) {}
            }
        }
    }
    __syncthreads();  // spin confirmed for all prologue loads below
    if (iscomp && role != 1) p_cur = ldg_cg1(Pin + tid);  // row 0, coalesced
    if (!iscomp && role == 1) {
        int lane = tid - 416;
        if (lane < 25) {
            reinterpret_cast<float4*>(hbuf[0])[lane] =
                ldg_cg4(reinterpret_cast<const float4*>(g_H0) + lane);          // row 0
            hreg = ldg_cg4(reinterpret_cast<const float4*>(g_H0 + Hh) + lane);  // row 1
        }
    }
    __syncthreads();

    for (int t = 0; t < Nn; t++) {
        if (iscomp) {
            // distance-1 register prefetch of next additive row (availability
            // guaranteed by spin schedule: cnt >= t+3 at top of step t)
            float p_nxt = 0.f;
            const bool havep = (role != 1) && (t + 1 < Nn);
            if (havep) p_nxt = ldg_cg1(Pin + (t + 1) * Gg + tid);

            // ---- dot ----
            const float* hin = (role == 1) ? hbuf[t & 1] : h_sh[t & 1];
            const ulonglong2* h2 = reinterpret_cast<const ulonglong2*>(hin);
            unsigned long long a0 = 0ull, a1 = 0ull, a2 = 0ull, a3 = 0ull;
#pragma unroll
            for (int j = 0; j < 25; j++) {
                ulonglong2 hv = h2[j];  // LDS.128 broadcast
                if (j & 1) {
                    FMA2(a2, wv[2 * j], hv.x);
                    FMA2(a3, wv[2 * j + 1], hv.y);
                } else {
                    FMA2(a0, wv[2 * j], hv.x);
                    FMA2(a1, wv[2 * j + 1], hv.y);
                }
            }
            ADD2(a0, a0, a1);
            ADD2(a2, a2, a3);
            ADD2(a0, a0, a2);
            float a = unpack_sum(a0);

            if (role == 1) {
                // direct permuted store: position tid holds row r(tid) = C's contract
                __stcg(&g_P1[t * Gg + tid], a + bb);
            } else {
                float v = a + p_cur;
                float act = (g == 2) ? tanhap(v) : fmaf(0.5f, tanhap(0.5f * v), 0.5f);
                float vf = __shfl_sync(shmask, act, 1, 4);
                float vg = __shfl_sync(shmask, act, 2, 4);
                float vo = __shfl_sync(shmask, act, 3, 4);
                if (g == 0) {  // owner lane: own act = i gate
                    c = fmaf(vf, c, act * vg);
                    float hk = vo * tanhap(c);
                    h_sh[(t + 1) & 1][u] = hk;
                    if (role == 0) __stcg(&g_H0[t * Hh + u], hk);
                    else g_H1[t * Hh + u] = hk;
                }
            }
            p_cur = p_nxt;
        } else if (tid >= 416) {
            int lane = tid - 416;
            if (role == 0) {
                if (lane == 0 && (t & 7) == 0 && t > 0) st_rel(&g_cnt0, t);  // rows < t
            } else if (role == 1) {
                if (lane < 25) {
                    if (t + 1 < Nn)
                        reinterpret_cast<float4*>(hbuf[(t + 1) & 1])[lane] = hreg;  // STS (old data)
                    if (t + 2 < Nn)
                        hreg = ldg_cg4(reinterpret_cast<const float4*>(g_H0 + (t + 2) * Hh) + lane);
                } else if (lane == 25) {
                    if ((t & 7) == 0 && t > 0) st_rel(&g_cnt1, t);  // rows < t (stored in-step)
                } else if (lane == 26) {
                    if (t + 3 < Nn && seen < t + 4) {
                        while ((seen = ld_acq(&g_cnt0)) < t + 4) {}
                    }
                }
            } else {
                if (lane == 0 && t + 3 < Nn && seen < t + 4) {
                    while ((seen = ld_acq(&g_cnt1)) < t + 4) {}
                }
            }
        }
        __syncthreads();
    }
    // epilogue: final releases (loop's last barrier orders all stores)
    if (tid == 416) {
        if (role == 0) st_rel(&g_cnt0, Nn);
        else if (role == 1) st_rel(&g_cnt1, Nn);
    }
}

// ---------------- K5b: fold scorer weights + EA/EB/S ----------------
__global__ __launch_bounds__(1024) void score_vec(const float* __restrict__ Wh2h,
                                                  const float* __restrict__ bh2h,
                                                  const float* __restrict__ Wsc,
                                                  const float* __restrict__ bsc) {
    __shared__ float u_sh[2 * Hh + 1];
    __shared__ float red[Nn];
    int i = threadIdx.x;

    if (i < 200) {
        int k = (i < 100) ? i : i - 100;
        int which = (i < 100) ? 0 : 1;
        const float* base = Wh2h + which * 100 + k;
        float s = 0.f;
        for (int m = 0; m < Hh; m++) s = fmaf(base[m * 200], Wsc[m], s);
        u_sh[which * 100 + k] = s;
    } else if (i == 200) {
        float c0 = bsc[0];
        for (int m = 0; m < Hh; m++) c0 = fmaf(bh2h[m], Wsc[m], c0);
        u_sh[200] = c0;
    }
    __syncthreads();

    const float* h = g_H1 + i * Hh;
    float sA = 0.f, sB = 0.f;
    for (int j = 0; j < Hh; j++) {
        float hv = h[j];
        sA = fmaf(hv, u_sh[j], sA);
        sB = fmaf(hv, u_sh[100 + j], sB);
    }
    float ea = __expf(sA);
    float eb = __expf(sB + u_sh[200]);
    g_EA[i] = ea;
    g_EB[i] = eb;
    red[i] = ea;
    __syncthreads();
    for (int s = 512; s > 0; s >>= 1) {
        if (i < s) red[i] += red[i + s];
        __syncthreads();
    }
    if (i == 0) g_S = red[0];
}

// ---------------- K5c: scores[i][j] = EA[i]*EB[j] / (S*EB[j] + eps) ----------------
__global__ void fill_scores(float* __restrict__ out) {
    int i = blockIdx.x;
    float ea = g_EA[i];
    float S = g_S;
    for (int j = threadIdx.x; j < Nn; j += blockDim.x) {
        float eb = g_EB[j];
        out[i * Nn + j] = __fdividef(ea * eb, fmaf(S, eb, EPSV));
    }
}

// ---------------- K5d: labels ----------------
__global__ void fill_labels(const float* __restrict__ Wlab, const float* __restrict__ blab,
                            float* __restrict__ out) {
    __shared__ float hsh[Hh];
    __shared__ float esh[Ll];
    int r = blockIdx.x;  // 0..1022
    int tid = threadIdx.x;
    const float* h = g_H1 + (r + 1) * Hh;
    for (int j = tid; j < Hh; j += 64) hsh[j] = h[j];
    __syncthreads();
    if (tid < Ll) {
        float a = blab[tid];
        const float* wr = Wlab + tid * Hh;
        for (int j = 0; j < Hh; j++) a = fmaf(hsh[j], wr[j], a);
        esh[tid] = __expf(a);
    }
    __syncthreads();
    if (tid < Ll) {
        float s = 0.f;
        for (int j = 0; j < Ll; j++) s += esh[j];
        out[Nn * Nn + r * Ll + tid] = __fdividef(esh[tid], s + EPSV);
    }
}

// ---------------- launch ----------------
extern "C" void kernel_launch(void* const* d_in, const int* in_sizes, int n_in,
                              void* d_out, int out_size) {
    const int* wi = (const int*)d_in[0];
    const int* ti = (const int*)d_in[1];
    const float* wt = (const float*)d_in[2];
    const float* tt = (const float*)d_in[3];
    const float* Wih0 = (const float*)d_in[4];
    const float* Whh0 = (const float*)d_in[5];
    const float* bih0 = (const float*)d_in[6];
    const float* bhh0 = (const float*)d_in[7];
    const float* Wih1 = (const float*)d_in[8];
    const float* Whh1 = (const float*)d_in[9];
    const float* bih1 = (const float*)d_in[10];
    const float* bhh1 = (const float*)d_in[11];
    const float* Wh2h = (const float*)d_in[12];
    const float* bh2h = (const float*)d_in[13];
    const float* Wsc = (const float*)d_in[14];
    const float* bsc = (const float*)d_in[15];
    const float* Wlab = (const float*)d_in[16];
    const float* blab = (const float*)d_in[17];
    float* out = (float*)d_out;

    float *pE, *pP;
    cudaGetSymbolAddress((void**)&pE, g_E);
    cudaGetSymbolAddress((void**)&pP, g_P);

    dim3 gg(13, 16);

    gather_emb<<<Nn, 128>>>(wi, ti, wt, tt);
    zero_cnt<<<1, 32>>>();
    gemm_bias<<<gg, 256>>>(pE, Wih0, bih0, bhh0, pP, KE);
    lstm_pipe<<<3, 448>>>(Whh0, Wih1, Whh1, bih1, bhh1);
    score_vec<<<1, 1024>>>(Wh2h, bh2h, Wsc, bsc);
    fill_scores<<<Nn, 256>>>(out);
    fill_labels<<<Nn - 1, 64>>>(Wlab, blab, out);
}

// round 14
// speedup vs baseline: 1.0176x; 1.0134x over previous
#include <cuda_runtime.h>
#include <cstdint>

#define Nn 1024
#define Hh 100
#define Gg 400
#define KE 125
#define Ll 40
#define EPSV 1e-20f

// ---------------- scratch (device globals; no allocation allowed) ----------------
__device__ float g_E[Nn * KE];   // embeddings [1024,125]
__device__ float g_P[Nn * Gg];   // layer0 input projection (gemm output)
__device__ float g_P1[Nn * Gg];  // layer1 input projection (stage B output)
__device__ float g_H0[Nn * Hh];  // layer0 hidden states
__device__ float g_H1[Nn * Hh];  // layer1 hidden states
__device__ int g_cnt0;           // h0 rows < cnt0 published
__device__ int g_cnt1;           // P1 rows < cnt1 published
__device__ float g_EA[Nn];
__device__ float g_EB[Nn];
__device__ float g_S;

// ---------------- helpers ----------------
__device__ __forceinline__ float tanhap(float x) {
    float r;
    asm("tanh.approx.f32 %0, %1;" : "=f"(r) : "f"(x));
    return r;
}
#define FMA2(acc, a, b) asm("fma.rn.f32x2 %0, %1, %2, %0;" : "+l"(acc) : "l"(a), "l"(b))
__device__ __forceinline__ float unpack_sum(unsigned long long v) {
    float lo, hi;
    asm("mov.b64 {%0, %1}, %2;" : "=f"(lo), "=f"(hi) : "l"(v));
    return lo + hi;
}
__device__ __forceinline__ int ld_acq(const int* p) {
    int v;
    asm volatile("ld.acquire.gpu.b32 %0, [%1];" : "=r"(v) : "l"(p) : "memory");
    return v;
}
__device__ __forceinline__ void st_rel(int* p, int v) {
    asm volatile("st.release.gpu.b32 [%0], %1;" :: "l"(p), "r"(v) : "memory");
}
__device__ __forceinline__ float4 ldg_cg4(const float4* p) {
    float4 v;
    asm volatile("ld.global.cg.v4.f32 {%0,%1,%2,%3}, [%4];"
                 : "=f"(v.x), "=f"(v.y), "=f"(v.z), "=f"(v.w) : "l"(p));
    return v;
}
__device__ __forceinline__ float ldg_cg1(const float* p) {
    float v;
    asm volatile("ld.global.cg.f32 %0, [%1];" : "=f"(v) : "l"(p));
    return v;
}

// ---------------- K0: embedding gather (+ counter reset, block 0) ----------------
__global__ void gather_emb(const int* __restrict__ wi, const int* __restrict__ ti,
                           const float* __restrict__ wt, const float* __restrict__ tt) {
    int t = blockIdx.x;
    if (t == 0 && threadIdx.x == 0) { g_cnt0 = 0; g_cnt1 = 0; }  // reset per launch/replay
    int w = wi[t];
    int g = ti[t];
    for (int j = threadIdx.x; j < KE; j += blockDim.x)
        g_E[t * KE + j] = (j < 100) ? wt[w * 100 + j] : tt[g * 25 + (j - 100)];
}

// ---------------- K1: P0 = E @ Wih0^T + b_ih0 + b_hh0 ----------------
__global__ __launch_bounds__(256) void gemm_bias(const float* __restrict__ X,
                                                 const float* __restrict__ W,
                                                 const float* __restrict__ b1,
                                                 const float* __restrict__ b2,
                                                 float* __restrict__ C, int K) {
    __shared__ float Xs[64 * 127];
    __shared__ float Ws[32 * 127];
    int m0 = blockIdx.y * 64;
    int n0 = blockIdx.x * 32;
    int tid = threadIdx.x;

    for (int idx = tid; idx < 64 * K; idx += 256) {
        int r = idx / K, c = idx - r * K;
        Xs[r * 127 + c] = X[(m0 + r) * K + c];
    }
    for (int idx = tid; idx < 32 * K; idx += 256) {
        int r = idx / K, c = idx - r * K;
        int n = n0 + r;
        Ws[r * 127 + c] = (n < Gg) ? W[n * K + c] : 0.f;
    }
    __syncthreads();

    int ty = tid >> 5, tx = tid & 31;
    float acc[8] = {0, 0, 0, 0, 0, 0, 0, 0};
    for (int k = 0; k < K; k++) {
        float wv = Ws[tx * 127 + k];
#pragma unroll
        for (int r = 0; r < 8; r++)
            acc[r] = fmaf(Xs[(ty + 8 * r) * 127 + k], wv, acc[r]);
    }
    int n = n0 + tx;
    if (n < Gg) {
        float bb = b1[n] + b2[n];
#pragma unroll
        for (int r = 0; r < 8; r++)
            C[(m0 + ty + 8 * r) * Gg + n] = acc[r] + bb;
    }
}

// ---------------- K2: 3-stage LSTM pipeline (R10-exact structure + hoisted pbuf read) ----------------
// grid=3 x 448 (13 compute warps + 1 comm warp). role 0 (A): layer0 recurrence;
// 1 (B): layer1 input proj; 2 (C): layer1 recurrence.
// Compute thread tid<400: unit u=tid>>2, gate g=tid&3, row r=g*100+u.
// Handoff: monotonic counters, 1 st.release per 8 steps, lookahead spin (R10-proven).
// ONLY change vs R10: the additive value pbuf[t&1][r] is loaded BEFORE the dot
// (it was written at the end of step t-1, so it's ready; the 29-cyc LDS now hides
// under the ~300-cyc dot instead of sitting on the activation chain).
__global__ __launch_bounds__(448, 1) void lstm_pipe(const float* __restrict__ Whh0,
                                                    const float* __restrict__ Wih1,
                                                    const float* __restrict__ Whh1,
                                                    const float* __restrict__ bih1,
                                                    const float* __restrict__ bhh1) {
    __shared__ __align__(16) float h_sh[2][Hh];   // A/C recurrent state (double buffered)
    __shared__ __align__(16) float hbuf[2][Hh];   // B: staged h0 rows
    __shared__ __align__(16) float pbuf[2][Gg];   // A/C: staged additive rows
    __shared__ __align__(16) float obuf[2][Gg];   // B: gate outputs awaiting writeback

    const int role = blockIdx.x;
    const int tid = threadIdx.x;
    const bool iscomp = tid < 400;
    const int u = tid >> 2;      // unit 0..99
    const int g = tid & 3;       // gate 0:i 1:f 2:g 3:o
    const int r = g * 100 + u;   // weight row
    const unsigned shmask = (tid < 384) ? 0xffffffffu : 0x0000ffffu;

    const float* W = (role == 0) ? Whh0 : (role == 1) ? Wih1 : Whh1;
    const float* Pin = (role == 0) ? g_P : g_P1;

    // full weight row in registers: 25 ulonglong2 = 50 u64 regs
    unsigned long long wv[50];
    if (iscomp) {
        const ulonglong2* Wr = reinterpret_cast<const ulonglong2*>(W + r * Hh);
#pragma unroll
        for (int j = 0; j < 25; j++) {
            ulonglong2 v = Wr[j];
            wv[2 * j] = v.x;
            wv[2 * j + 1] = v.y;
        }
    }
    float bb = 0.f;
    if (role == 1 && iscomp) bb = bih1[r] + bhh1[r];
    float c = 0.f;
    if (role != 1 && tid < Hh) h_sh[0][tid] = 0.f;

    int seen = 0;  // comm lane0's cached counter value

    // ---- prologue: rows {0,1} availability; B stages h0 row 0 ----
    if (!iscomp && tid >= 416) {
        int lane = tid - 416;
        if (role == 1) {
            if (lane == 0) {
                while ((seen = ld_acq(&g_cnt0)) < 2) {}
            }
            __syncwarp();
            if (lane < 25)
                reinterpret_cast<float4*>(hbuf[0])[lane] =
                    ldg_cg4(reinterpret_cast<const float4*>(g_H0) + lane);
        } else if (role == 2) {
            if (lane == 0) {
                while ((seen = ld_acq(&g_cnt1)) < 2) {}
            }
        }
    }
    __syncthreads();
    if (role != 1 && iscomp) pbuf[0][tid] = ldg_cg1(Pin + tid);  // coalesced row 0
    __syncthreads();

    for (int t = 0; t < Nn; t++) {
        if (iscomp) {
            // B: coalesced writeback of last step's P1 row
            if (role == 1 && t >= 1)
                __stcg(&g_P1[(t - 1) * Gg + tid], obuf[(t - 1) & 1][tid]);
            // A/C: coalesced prefetch of next additive row (availability confirmed
            // by comm lane0's spin at step t-1)
            float pn = 0.f;
            const bool havep = (role != 1) && (t + 1 < Nn);
            if (havep) pn = ldg_cg1(Pin + (t + 1) * Gg + tid);
            // HOIST: this step's additive value (written end of step t-1; ready now).
            float pv = (role != 1) ? pbuf[t & 1][r] : 0.f;

            const float* hin = (role == 1) ? hbuf[t & 1] : h_sh[t & 1];
            const ulonglong2* h2 = reinterpret_cast<const ulonglong2*>(hin);
            unsigned long long a0 = 0ull, a1 = 0ull, a2 = 0ull, a3 = 0ull;
#pragma unroll
            for (int j = 0; j < 25; j++) {
                ulonglong2 hv = h2[j];  // LDS.128 broadcast (all lanes same addr)
                if (j & 1) {
                    FMA2(a2, wv[2 * j], hv.x);
                    FMA2(a3, wv[2 * j + 1], hv.y);
                } else {
                    FMA2(a0, wv[2 * j], hv.x);
                    FMA2(a1, wv[2 * j + 1], hv.y);
                }
            }
            float a = (unpack_sum(a0) + unpack_sum(a1)) + (unpack_sum(a2) + unpack_sum(a3));

            if (role == 1) {
                obuf[t & 1][r] = a + bb;  // STS; coalesced STG next step
            } else {
                float v = a + pv;
                float act = (g == 2) ? tanhap(v) : fmaf(0.5f, tanhap(0.5f * v), 0.5f);
                // gate exchange within the 4-lane unit group
                float vf = __shfl_sync(shmask, act, 1, 4);
                float vg = __shfl_sync(shmask, act, 2, 4);
                float vo = __shfl_sync(shmask, act, 3, 4);
                if (g == 0) {  // owner lane: own act = i gate
                    c = fmaf(vf, c, act * vg);
                    float hk = vo * tanhap(c);
                    h_sh[(t + 1) & 1][u] = hk;  // next buffer: no race with dot readers
                    if (role == 0) __stcg(&g_H0[t * Hh + u], hk);
                    else g_H1[t * Hh + u] = hk;
                }
            }
            if (havep) pbuf[(t + 1) & 1][tid] = pn;  // STS after dot: LDG latency hidden
        } else if (tid >= 416) {
            int lane = tid - 416;
            if (role == 0) {
                if (lane == 0 && (t & 7) == 0 && t > 0) st_rel(&g_cnt0, t);  // rows < t
            } else if (role == 1) {
                if (lane == 0) {
                    if ((t & 7) == 0 && t > 0) st_rel(&g_cnt1, t - 1);  // rows < t-1
                    if (t + 2 < Nn && seen < t + 3) {
                        while ((seen = ld_acq(&g_cnt0)) < t + 3) {}
                    }
                }
                // stage h0[t+1] (guarded by lane0's spin at step t-1: seen >= t+2)
                if (lane < 25 && t + 1 < Nn)
                    reinterpret_cast<float4*>(hbuf[(t + 1) & 1])[lane] =
                        ldg_cg4(reinterpret_cast<const float4*>(g_H0 + (t + 1) * Hh) + lane);
            } else {
                if (lane == 0 && t + 2 < Nn && seen < t + 3) {
                    while ((seen = ld_acq(&g_cnt1)) < t + 3) {}
                }
            }
        }
        __syncthreads();
    }
    // epilogue: B writes back its final row; final releases
    if (role == 1 && iscomp)
        __stcg(&g_P1[(Nn - 1) * Gg + tid], obuf[(Nn - 1) & 1][tid]);
    __syncthreads();
    if (tid == 416) {
        if (role == 0) st_rel(&g_cnt0, Nn);
        else if (role == 1) st_rel(&g_cnt1, Nn);
    }
}

// ---------------- K5b: fold scorer weights + EA/EB/S ----------------
__global__ __launch_bounds__(1024) void score_vec(const float* __restrict__ Wh2h,
                                                  const float* __restrict__ bh2h,
                                                  const float* __restrict__ Wsc,
                                                  const float* __restrict__ bsc) {
    __shared__ float u_sh[2 * Hh + 1];
    __shared__ float red[Nn];
    int i = threadIdx.x;

    if (i < 200) {
        int k = (i < 100) ? i : i - 100;
        int which = (i < 100) ? 0 : 1;
        const float* base = Wh2h + which * 100 + k;
        float s = 0.f;
        for (int m = 0; m < Hh; m++) s = fmaf(base[m * 200], Wsc[m], s);
        u_sh[which * 100 + k] = s;
    } else if (i == 200) {
        float c0 = bsc[0];
        for (int m = 0; m < Hh; m++) c0 = fmaf(bh2h[m], Wsc[m], c0);
        u_sh[200] = c0;
    }
    __syncthreads();

    const float* h = g_H1 + i * Hh;
    float sA = 0.f, sB = 0.f;
    for (int j = 0; j < Hh; j++) {
        float hv = h[j];
        sA = fmaf(hv, u_sh[j], sA);
        sB = fmaf(hv, u_sh[100 + j], sB);
    }
    float ea = __expf(sA);
    float eb = __expf(sB + u_sh[200]);
    g_EA[i] = ea;
    g_EB[i] = eb;
    red[i] = ea;
    __syncthreads();
    for (int s = 512; s > 0; s >>= 1) {
        if (i < s) red[i] += red[i + s];
        __syncthreads();
    }
    if (i == 0) g_S = red[0];
}

// ---------------- K5c: scores[i][j] = EA[i]*EB[j] / (S*EB[j] + eps) ----------------
__global__ void fill_scores(float* __restrict__ out) {
    int i = blockIdx.x;
    float ea = g_EA[i];
    float S = g_S;
    for (int j = threadIdx.x; j < Nn; j += blockDim.x) {
        float eb = g_EB[j];
        out[i * Nn + j] = __fdividef(ea * eb, fmaf(S, eb, EPSV));
    }
}

// ---------------- K5d: labels ----------------
__global__ void fill_labels(const float* __restrict__ Wlab, const float* __restrict__ blab,
                            float* __restrict__ out) {
    __shared__ float hsh[Hh];
    __shared__ float esh[Ll];
    int r = blockIdx.x;  // 0..1022
    int tid = threadIdx.x;
    const float* h = g_H1 + (r + 1) * Hh;
    for (int j = tid; j < Hh; j += 64) hsh[j] = h[j];
    __syncthreads();
    if (tid < Ll) {
        float a = blab[tid];
        const float* wr = Wlab + tid * Hh;
        for (int j = 0; j < Hh; j++) a = fmaf(hsh[j], wr[j], a);
        esh[tid] = __expf(a);
    }
    __syncthreads();
    if (tid < Ll) {
        float s = 0.f;
        for (int j = 0; j < Ll; j++) s += esh[j];
        out[Nn * Nn + r * Ll + tid] = __fdividef(esh[tid], s + EPSV);
    }
}

// ---------------- launch ----------------
extern "C" void kernel_launch(void* const* d_in, const int* in_sizes, int n_in,
                              void* d_out, int out_size) {
    const int* wi = (const int*)d_in[0];
    const int* ti = (const int*)d_in[1];
    const float* wt = (const float*)d_in[2];
    const float* tt = (const float*)d_in[3];
    const float* Wih0 = (const float*)d_in[4];
    const float* Whh0 = (const float*)d_in[5];
    const float* bih0 = (const float*)d_in[6];
    const float* bhh0 = (const float*)d_in[7];
    const float* Wih1 = (const float*)d_in[8];
    const float* Whh1 = (const float*)d_in[9];
    const float* bih1 = (const float*)d_in[10];
    const float* bhh1 = (const float*)d_in[11];
    const float* Wh2h = (const float*)d_in[12];
    const float* bh2h = (const float*)d_in[13];
    const float* Wsc = (const float*)d_in[14];
    const float* bsc = (const float*)d_in[15];
    const float* Wlab = (const float*)d_in[16];
    const float* blab = (const float*)d_in[17];
    float* out = (float*)d_out;

    float *pE, *pP;
    cudaGetSymbolAddress((void**)&pE, g_E);
    cudaGetSymbolAddress((void**)&pP, g_P);

    dim3 gg(13, 16);

    gather_emb<<<Nn, 128>>>(wi, ti, wt, tt);
    gemm_bias<<<gg, 256>>>(pE, Wih0, bih0, bhh0, pP, KE);
    lstm_pipe<<<3, 448>>>(Whh0, Wih1, Whh1, bih1, bhh1);
    score_vec<<<1, 1024>>>(Wh2h, bh2h, Wsc, bsc);
    fill_scores<<<Nn, 256>>>(out);
    fill_labels<<<Nn - 1, 64>>>(Wlab, blab, out);
}

// round 16
// speedup vs baseline: 1.2072x; 1.1863x over previous
#include <cuda_runtime.h>
#include <cstdint>

#define Nn 1024
#define Hh 100
#define Gg 400
#define KE 125
#define Ll 40
#define EPSV 1e-20f

// ---------------- scratch (device globals; no allocation allowed) ----------------
__device__ float g_E[Nn * KE];   // embeddings [1024,125]
__device__ float g_P[Nn * Gg];   // layer0 input projection (gemm output)
__device__ float g_P1[Nn * Gg];  // layer1 input projection (stage B output)
__device__ float g_H0[Nn * Hh];  // layer0 hidden states
__device__ float g_H1[Nn * Hh];  // layer1 hidden states
__device__ int g_cnt0;           // h0 rows < cnt0 published
__device__ int g_cnt1;           // P1 rows < cnt1 published
__device__ float g_EA[Nn];
__device__ float g_EB[Nn];
__device__ float g_S;

// ---------------- helpers ----------------
__device__ __forceinline__ float tanhap(float x) {
    float r;
    asm("tanh.approx.f32 %0, %1;" : "=f"(r) : "f"(x));
    return r;
}
#define FMA2(acc, a, b) asm("fma.rn.f32x2 %0, %1, %2, %0;" : "+l"(acc) : "l"(a), "l"(b))
__device__ __forceinline__ float unpack_sum(unsigned long long v) {
    float lo, hi;
    asm("mov.b64 {%0, %1}, %2;" : "=f"(lo), "=f"(hi) : "l"(v));
    return lo + hi;
}
__device__ __forceinline__ int ld_acq(const int* p) {
    int v;
    asm volatile("ld.acquire.gpu.b32 %0, [%1];" : "=r"(v) : "l"(p) : "memory");
    return v;
}
__device__ __forceinline__ void st_rel(int* p, int v) {
    asm volatile("st.release.gpu.b32 [%0], %1;" :: "l"(p), "r"(v) : "memory");
}
__device__ __forceinline__ float4 ldg_cg4(const float4* p) {
    float4 v;
    asm volatile("ld.global.cg.v4.f32 {%0,%1,%2,%3}, [%4];"
                 : "=f"(v.x), "=f"(v.y), "=f"(v.z), "=f"(v.w) : "l"(p));
    return v;
}
__device__ __forceinline__ float ldg_cg1(const float* p) {
    float v;
    asm volatile("ld.global.cg.f32 %0, [%1];" : "=f"(v) : "l"(p));
    return v;
}

// ---------------- K0: embedding gather (R10-exact) ----------------
__global__ void gather_emb(const int* __restrict__ wi, const int* __restrict__ ti,
                           const float* __restrict__ wt, const float* __restrict__ tt) {
    int t = blockIdx.x;
    int w = wi[t];
    int g = ti[t];
    for (int j = threadIdx.x; j < KE; j += blockDim.x)
        g_E[t * KE + j] = (j < 100) ? wt[w * 100 + j] : tt[g * 25 + (j - 100)];
}

// ---------------- K0b: reset progress counters (R10-exact) ----------------
__global__ void zero_cnt() {
    if (threadIdx.x == 0) { g_cnt0 = 0; g_cnt1 = 0; }
}

// ---------------- K1: P0 = E @ Wih0^T + b_ih0 + b_hh0 (R10-exact) ----------------
__global__ __launch_bounds__(256) void gemm_bias(const float* __restrict__ X,
                                                 const float* __restrict__ W,
                                                 const float* __restrict__ b1,
                                                 const float* __restrict__ b2,
                                                 float* __restrict__ C, int K) {
    __shared__ float Xs[64 * 127];
    __shared__ float Ws[32 * 127];
    int m0 = blockIdx.y * 64;
    int n0 = blockIdx.x * 32;
    int tid = threadIdx.x;

    for (int idx = tid; idx < 64 * K; idx += 256) {
        int r = idx / K, c = idx - r * K;
        Xs[r * 127 + c] = X[(m0 + r) * K + c];
    }
    for (int idx = tid; idx < 32 * K; idx += 256) {
        int r = idx / K, c = idx - r * K;
        int n = n0 + r;
        Ws[r * 127 + c] = (n < Gg) ? W[n * K + c] : 0.f;
    }
    __syncthreads();

    int ty = tid >> 5, tx = tid & 31;
    float acc[8] = {0, 0, 0, 0, 0, 0, 0, 0};
    for (int k = 0; k < K; k++) {
        float wv = Ws[tx * 127 + k];
#pragma unroll
        for (int r = 0; r < 8; r++)
            acc[r] = fmaf(Xs[(ty + 8 * r) * 127 + k], wv, acc[r]);
    }
    int n = n0 + tx;
    if (n < Gg) {
        float bb = b1[n] + b2[n];
#pragma unroll
        for (int r = 0; r < 8; r++)
            C[(m0 + ty + 8 * r) * Gg + n] = acc[r] + bb;
    }
}

// ---------------- K2: 3-stage LSTM pipeline (R10-EXACT, byte-for-byte) ----------------
__global__ __launch_bounds__(448, 1) void lstm_pipe(const float* __restrict__ Whh0,
                                                    const float* __restrict__ Wih1,
                                                    const float* __restrict__ Whh1,
                                                    const float* __restrict__ bih1,
                                                    const float* __restrict__ bhh1) {
    __shared__ __align__(16) float h_sh[2][Hh];   // A/C recurrent state (double buffered)
    __shared__ __align__(16) float hbuf[2][Hh];   // B: staged h0 rows
    __shared__ __align__(16) float pbuf[2][Gg];   // A/C: staged additive rows
    __shared__ __align__(16) float obuf[2][Gg];   // B: gate outputs awaiting writeback

    const int role = blockIdx.x;
    const int tid = threadIdx.x;
    const bool iscomp = tid < 400;
    const int u = tid >> 2;      // unit 0..99
    const int g = tid & 3;       // gate 0:i 1:f 2:g 3:o
    const int r = g * 100 + u;   // weight row
    const unsigned shmask = (tid < 384) ? 0xffffffffu : 0x0000ffffu;

    const float* W = (role == 0) ? Whh0 : (role == 1) ? Wih1 : Whh1;
    const float* Pin = (role == 0) ? g_P : g_P1;

    unsigned long long wv[50];
    if (iscomp) {
        const ulonglong2* Wr = reinterpret_cast<const ulonglong2*>(W + r * Hh);
#pragma unroll
        for (int j = 0; j < 25; j++) {
            ulonglong2 v = Wr[j];
            wv[2 * j] = v.x;
            wv[2 * j + 1] = v.y;
        }
    }
    float bb = 0.f;
    if (role == 1 && iscomp) bb = bih1[r] + bhh1[r];
    float c = 0.f;
    if (role != 1 && tid < Hh) h_sh[0][tid] = 0.f;

    int seen = 0;  // comm lane0's cached counter value

    // ---- prologue: rows {0,1} availability; B stages h0 row 0 ----
    if (!iscomp && tid >= 416) {
        int lane = tid - 416;
        if (role == 1) {
            if (lane == 0) {
                while ((seen = ld_acq(&g_cnt0)) < 2) {}
            }
            __syncwarp();
            if (lane < 25)
                reinterpret_cast<float4*>(hbuf[0])[lane] =
                    ldg_cg4(reinterpret_cast<const float4*>(g_H0) + lane);
        } else if (role == 2) {
            if (lane == 0) {
                while ((seen = ld_acq(&g_cnt1)) < 2) {}
            }
        }
    }
    __syncthreads();
    if (role != 1 && iscomp) pbuf[0][tid] = ldg_cg1(Pin + tid);  // coalesced row 0
    __syncthreads();

    for (int t = 0; t < Nn; t++) {
        if (iscomp) {
            // B: coalesced writeback of last step's P1 row
            if (role == 1 && t >= 1)
                __stcg(&g_P1[(t - 1) * Gg + tid], obuf[(t - 1) & 1][tid]);
            // A/C: coalesced prefetch of next additive row
            float pn = 0.f;
            const bool havep = (role != 1) && (t + 1 < Nn);
            if (havep) pn = ldg_cg1(Pin + (t + 1) * Gg + tid);

            const float* hin = (role == 1) ? hbuf[t & 1] : h_sh[t & 1];
            const ulonglong2* h2 = reinterpret_cast<const ulonglong2*>(hin);
            unsigned long long a0 = 0ull, a1 = 0ull, a2 = 0ull, a3 = 0ull;
#pragma unroll
            for (int j = 0; j < 25; j++) {
                ulonglong2 hv = h2[j];  // LDS.128 broadcast
                if (j & 1) {
                    FMA2(a2, wv[2 * j], hv.x);
                    FMA2(a3, wv[2 * j + 1], hv.y);
                } else {
                    FMA2(a0, wv[2 * j], hv.x);
                    FMA2(a1, wv[2 * j + 1], hv.y);
                }
            }
            float a = (unpack_sum(a0) + unpack_sum(a1)) + (unpack_sum(a2) + unpack_sum(a3));

            if (role == 1) {
                obuf[t & 1][r] = a + bb;  // STS; coalesced STG next step
            } else {
                float v = a + pbuf[t & 1][r];
                float act = (g == 2) ? tanhap(v) : fmaf(0.5f, tanhap(0.5f * v), 0.5f);
                float vf = __shfl_sync(shmask, act, 1, 4);
                float vg = __shfl_sync(shmask, act, 2, 4);
                float vo = __shfl_sync(shmask, act, 3, 4);
                if (g == 0) {  // owner lane: own act = i gate
                    c = fmaf(vf, c, act * vg);
                    float hk = vo * tanhap(c);
                    h_sh[(t + 1) & 1][u] = hk;
                    if (role == 0) __stcg(&g_H0[t * Hh + u], hk);
                    else g_H1[t * Hh + u] = hk;
                }
            }
            if (havep) pbuf[(t + 1) & 1][tid] = pn;  // STS after dot: LDG latency hidden
        } else if (tid >= 416) {
            int lane = tid - 416;
            if (role == 0) {
                if (lane == 0 && (t & 7) == 0 && t > 0) st_rel(&g_cnt0, t);  // rows < t
            } else if (role == 1) {
                if (lane == 0) {
                    if ((t & 7) == 0 && t > 0) st_rel(&g_cnt1, t - 1);  // rows < t-1
                    if (t + 2 < Nn && seen < t + 3) {
                        while ((seen = ld_acq(&g_cnt0)) < t + 3) {}
                    }
                }
                if (lane < 25 && t + 1 < Nn)
                    reinterpret_cast<float4*>(hbuf[(t + 1) & 1])[lane] =
                        ldg_cg4(reinterpret_cast<const float4*>(g_H0 + (t + 1) * Hh) + lane);
            } else {
                if (lane == 0 && t + 2 < Nn && seen < t + 3) {
                    while ((seen = ld_acq(&g_cnt1)) < t + 3) {}
                }
            }
        }
        __syncthreads();
    }
    // epilogue: B writes back its final row; final releases
    if (role == 1 && iscomp)
        __stcg(&g_P1[(Nn - 1) * Gg + tid], obuf[(Nn - 1) & 1][tid]);
    __syncthreads();
    if (tid == 416) {
        if (role == 0) st_rel(&g_cnt0, Nn);
        else if (role == 1) st_rel(&g_cnt1, Nn);
    }
}

// ---------------- K5b: fold scorer weights + EA/EB/S (float4 h reads; 36->~12us) ----------------
__global__ __launch_bounds__(1024) void score_vec(const float* __restrict__ Wh2h,
                                                  const float* __restrict__ bh2h,
                                                  const float* __restrict__ Wsc,
                                                  const float* __restrict__ bsc) {
    __shared__ __align__(16) float u_sh[2 * Hh + 4];
    __shared__ float red[Nn];
    int i = threadIdx.x;

    if (i < 200) {
        int k = (i < 100) ? i : i - 100;
        int which = (i < 100) ? 0 : 1;
        const float* base = Wh2h + which * 100 + k;
        float s = 0.f;
        for (int m = 0; m < Hh; m++) s = fmaf(base[m * 200], Wsc[m], s);
        u_sh[which * 100 + k] = s;
    } else if (i == 200) {
        float c0 = bsc[0];
        for (int m = 0; m < Hh; m++) c0 = fmaf(bh2h[m], Wsc[m], c0);
        u_sh[200] = c0;
    }
    __syncthreads();

    // vectorized: row i of g_H1 is 400B (16B aligned); 25 LDG.128 instead of 100 LDG.32.
    // Accumulation order (j ascending, x,y,z,w) identical to the scalar version.
    const float4* h4 = reinterpret_cast<const float4*>(g_H1 + i * Hh);
    const float4* uA = reinterpret_cast<const float4*>(u_sh);
    const float4* uB = reinterpret_cast<const float4*>(u_sh + 100);
    float sA = 0.f, sB = 0.f;
#pragma unroll
    for (int j = 0; j < 25; j++) {
        float4 hv = h4[j];
        float4 ua = uA[j];
        float4 ub = uB[j];
        sA = fmaf(hv.x, ua.x, sA); sA = fmaf(hv.y, ua.y, sA);
        sA = fmaf(hv.z, ua.z, sA); sA = fmaf(hv.w, ua.w, sA);
        sB = fmaf(hv.x, ub.x, sB); sB = fmaf(hv.y, ub.y, sB);
        sB = fmaf(hv.z, ub.z, sB); sB = fmaf(hv.w, ub.w, sB);
    }
    float ea = __expf(sA);
    float eb = __expf(sB + u_sh[200]);
    g_EA[i] = ea;
    g_EB[i] = eb;
    red[i] = ea;
    __syncthreads();
    for (int s = 512; s > 0; s >>= 1) {
        if (i < s) red[i] += red[i + s];
        __syncthreads();
    }
    if (i == 0) g_S = red[0];
}

// ---------------- K5c: scores[i][j] = EA[i]*EB[j] / (S*EB[j] + eps) ----------------
__global__ void fill_scores(float* __restrict__ out) {
    int i = blockIdx.x;
    float ea = g_EA[i];
    float S = g_S;
    for (int j = threadIdx.x; j < Nn; j += blockDim.x) {
        float eb = g_EB[j];
        out[i * Nn + j] = __fdividef(ea * eb, fmaf(S, eb, EPSV));
    }
}

// ---------------- K5d: labels ----------------
__global__ void fill_labels(const float* __restrict__ Wlab, const float* __restrict__ blab,
                            float* __restrict__ out) {
    __shared__ float hsh[Hh];
    __shared__ float esh[Ll];
    int r = blockIdx.x;  // 0..1022
    int tid = threadIdx.x;
    const float* h = g_H1 + (r + 1) * Hh;
    for (int j = tid; j < Hh; j += 64) hsh[j] = h[j];
    __syncthreads();
    if (tid < Ll) {
        float a = blab[tid];
        const float* wr = Wlab + tid * Hh;
        for (int j = 0; j < Hh; j++) a = fmaf(hsh[j], wr[j], a);
        esh[tid] = __expf(a);
    }
    __syncthreads();
    if (tid < Ll) {
        float s = 0.f;
        for (int j = 0; j < Ll; j++) s += esh[j];
        out[Nn * Nn + r * Ll + tid] = __fdividef(esh[tid], s + EPSV);
    }
}

// ---------------- launch ----------------
extern "C" void kernel_launch(void* const* d_in, const int* in_sizes, int n_in,
                              void* d_out, int out_size) {
    const int* wi = (const int*)d_in[0];
    const int* ti = (const int*)d_in[1];
    const float* wt = (const float*)d_in[2];
    const float* tt = (const float*)d_in[3];
    const float* Wih0 = (const float*)d_in[4];
    const float* Whh0 = (const float*)d_in[5];
    const float* bih0 = (const float*)d_in[6];
    const float* bhh0 = (const float*)d_in[7];
    const float* Wih1 = (const float*)d_in[8];
    const float* Whh1 = (const float*)d_in[9];
    const float* bih1 = (const float*)d_in[10];
    const float* bhh1 = (const float*)d_in[11];
    const float* Wh2h = (const float*)d_in[12];
    const float* bh2h = (const float*)d_in[13];
    const float* Wsc = (const float*)d_in[14];
    const float* bsc = (const float*)d_in[15];
    const float* Wlab = (const float*)d_in[16];
    const float* blab = (const float*)d_in[17];
    float* out = (float*)d_out;

    float *pE, *pP;
    cudaGetSymbolAddress((void**)&pE, g_E);
    cudaGetSymbolAddress((void**)&pP, g_P);

    dim3 gg(13, 16);

    gather_emb<<<Nn, 128>>>(wi, ti, wt, tt);
    zero_cnt<<<1, 32>>>();
    gemm_bias<<<gg, 256>>>(pE, Wih0, bih0, bhh0, pP, KE);
    lstm_pipe<<<3, 448>>>(Whh0, Wih1, Whh1, bih1, bhh1);
    score_vec<<<1, 1024>>>(Wh2h, bh2h, Wsc, bsc);
    fill_scores<<<Nn, 256>>>(out);
    fill_labels<<<Nn - 1, 64>>>(Wlab, blab, out);
}